// round 3
// baseline (speedup 1.0000x reference)
#include <cuda_runtime.h>
#include <cstdint>

// ---------------------------------------------------------------------------
// NSHE: 3x per-type linear+ReLU encoders -> fused gcn GEMM (+bias) ->
//       edge-weighted gather + atomic scatter-add -> row L2 normalize.
//
// Shapes: N_A=100000 (K=512), N_B=60000 (K=256), N_C=40000 (K=128),
//         N=200000, D=64, E=3.2M.
// ---------------------------------------------------------------------------

#define MAX_N 200000
#define D 64

// Scratch for "support" = relu(feat@W+b) @ gcn_W + gcn_b   [N, 64]
__device__ float g_support[(size_t)MAX_N * D];

// ---------------------------------------------------------------------------
// Encoder + fused gcn GEMM.
// Block: 256 threads, computes a 64(rows) x 64(cols) tile.
// Phase 1: enc = relu(feat[64xK] @ W[Kx64] + b), K-chunked by 32.
// Phase 2: support = enc[64x64] @ gcnW[64x64] + gcnb, via smem staging.
// ---------------------------------------------------------------------------
template <int K>
__global__ __launch_bounds__(256) void encode_kernel(
    const float* __restrict__ feat,   // [n_rows, K]
    const float* __restrict__ W,      // [K, 64]
    const float* __restrict__ bias,   // [64]
    const float* __restrict__ gcnW,   // [64, 64]
    const float* __restrict__ gcnb,   // [64]
    int n_rows, int row_offset)
{
    // Phase-1 layout: sA = buf[0 .. 64*33), sB = buf[2112 .. 2112+32*64)
    // Phase-2 layout: sE = buf[0 .. 64*65)   (4160 floats both ways)
    __shared__ float buf[64 * 65];          // 4160 floats = 16.6 KB
    __shared__ float sGW[64 * 64];          // 16 KB
#define SA(m, k) buf[(m) * 33 + (k)]
#define SB(k, c) buf[2112 + (k) * 64 + (c)]
#define SE(m, k) buf[(m) * 65 + (k)]

    const int tid = threadIdx.x;
    const int tx = tid & 15;            // col group
    const int ty = tid >> 4;            // row group
    const int r0 = ty * 4;
    const int c0 = tx * 4;
    const int m0 = blockIdx.x * 64;

    // Cache gcn_W in smem (persists; disjoint from buf).
    #pragma unroll
    for (int i = tid; i < 64 * 64; i += 256)
        sGW[i] = gcnW[i];

    float acc[4][4];
    #pragma unroll
    for (int i = 0; i < 4; i++)
        #pragma unroll
        for (int j = 0; j < 4; j++)
            acc[i][j] = 0.0f;

    for (int kk = 0; kk < K; kk += 32) {
        // Load A tile: 64 rows x 32 k. Coalesced over k.
        #pragma unroll
        for (int j = 0; j < 8; j++) {
            int i = tid + j * 256;          // 0..2047
            int m = i >> 5;
            int k = i & 31;
            int row = m0 + m;
            SA(m, k) = (row < n_rows) ? feat[(size_t)row * K + kk + k] : 0.0f;
        }
        // Load B tile: 32 k x 64 cols. Coalesced over cols.
        #pragma unroll
        for (int j = 0; j < 8; j++) {
            int i = tid + j * 256;
            int k = i >> 6;
            int c = i & 63;
            SB(k, c) = W[(size_t)(kk + k) * 64 + c];
        }
        __syncthreads();

        #pragma unroll
        for (int k = 0; k < 32; k++) {
            float a0 = SA(r0 + 0, k);
            float a1 = SA(r0 + 1, k);
            float a2 = SA(r0 + 2, k);
            float a3 = SA(r0 + 3, k);
            float4 b = *reinterpret_cast<const float4*>(&SB(k, c0));
            acc[0][0] += a0 * b.x; acc[0][1] += a0 * b.y; acc[0][2] += a0 * b.z; acc[0][3] += a0 * b.w;
            acc[1][0] += a1 * b.x; acc[1][1] += a1 * b.y; acc[1][2] += a1 * b.z; acc[1][3] += a1 * b.w;
            acc[2][0] += a2 * b.x; acc[2][1] += a2 * b.y; acc[2][2] += a2 * b.z; acc[2][3] += a2 * b.w;
            acc[3][0] += a3 * b.x; acc[3][1] += a3 * b.y; acc[3][2] += a3 * b.z; acc[3][3] += a3 * b.w;
        }
        __syncthreads();
    }

    // Epilogue 1: +bias, ReLU, stage enc tile into smem (overwrites sA/sB).
    {
        const float4 bv = *reinterpret_cast<const float4*>(bias + c0);
        #pragma unroll
        for (int i = 0; i < 4; i++) {
            SE(r0 + i, c0 + 0) = fmaxf(acc[i][0] + bv.x, 0.0f);
            SE(r0 + i, c0 + 1) = fmaxf(acc[i][1] + bv.y, 0.0f);
            SE(r0 + i, c0 + 2) = fmaxf(acc[i][2] + bv.z, 0.0f);
            SE(r0 + i, c0 + 3) = fmaxf(acc[i][3] + bv.w, 0.0f);
        }
    }
    __syncthreads();

    // Phase 2: support = enc @ gcnW + gcnb.
    #pragma unroll
    for (int i = 0; i < 4; i++)
        #pragma unroll
        for (int j = 0; j < 4; j++)
            acc[i][j] = 0.0f;

    #pragma unroll
    for (int k = 0; k < 64; k++) {
        float a0 = SE(r0 + 0, k);
        float a1 = SE(r0 + 1, k);
        float a2 = SE(r0 + 2, k);
        float a3 = SE(r0 + 3, k);
        float4 b = *reinterpret_cast<const float4*>(&sGW[k * 64 + c0]);
        acc[0][0] += a0 * b.x; acc[0][1] += a0 * b.y; acc[0][2] += a0 * b.z; acc[0][3] += a0 * b.w;
        acc[1][0] += a1 * b.x; acc[1][1] += a1 * b.y; acc[1][2] += a1 * b.z; acc[1][3] += a1 * b.w;
        acc[2][0] += a2 * b.x; acc[2][1] += a2 * b.y; acc[2][2] += a2 * b.z; acc[2][3] += a2 * b.w;
        acc[3][0] += a3 * b.x; acc[3][1] += a3 * b.y; acc[3][2] += a3 * b.z; acc[3][3] += a3 * b.w;
    }

    // Epilogue 2: +gcnb, write to global support scratch.
    {
        const float4 gb = *reinterpret_cast<const float4*>(gcnb + c0);
        #pragma unroll
        for (int i = 0; i < 4; i++) {
            int row = m0 + r0 + i;
            if (row < n_rows) {
                float4 v = make_float4(acc[i][0] + gb.x, acc[i][1] + gb.y,
                                       acc[i][2] + gb.z, acc[i][3] + gb.w);
                *reinterpret_cast<float4*>(
                    &g_support[(size_t)(row_offset + row) * D + c0]) = v;
            }
        }
    }
#undef SA
#undef SB
#undef SE
}

// ---------------------------------------------------------------------------
// Zero the output accumulator.
// ---------------------------------------------------------------------------
__global__ void zero_kernel(float4* __restrict__ out, int n4)
{
    int i = blockIdx.x * blockDim.x + threadIdx.x;
    if (i < n4) out[i] = make_float4(0.0f, 0.0f, 0.0f, 0.0f);
}

// ---------------------------------------------------------------------------
// Edge scatter: out[dst] += support[src] * w.  16 threads per edge,
// float4 gather + vectorized red.global.add.v4.f32.
// ---------------------------------------------------------------------------
__global__ void scatter_kernel(const float* __restrict__ ew,
                               const int* __restrict__ es,
                               const int* __restrict__ ed,
                               float* __restrict__ out, int E)
{
    unsigned gid = blockIdx.x * blockDim.x + threadIdx.x;
    unsigned e = gid >> 4;
    if (e >= (unsigned)E) return;
    int c4 = (gid & 15) << 2;

    int s = __ldg(&es[e]);
    int d = __ldg(&ed[e]);
    float w = __ldg(&ew[e]);

    float4 v = *reinterpret_cast<const float4*>(&g_support[(size_t)s * D + c4]);
    float* p = out + (size_t)d * D + c4;
    asm volatile("red.global.add.v4.f32 [%0], {%1, %2, %3, %4};"
                 :: "l"(p), "f"(v.x * w), "f"(v.y * w), "f"(v.z * w), "f"(v.w * w)
                 : "memory");
}

// ---------------------------------------------------------------------------
// Row L2 normalize (one warp per row of 64).
// ---------------------------------------------------------------------------
__global__ void normalize_kernel(float* __restrict__ out, int N)
{
    int warp = (blockIdx.x * blockDim.x + threadIdx.x) >> 5;
    int lane = threadIdx.x & 31;
    if (warp >= N) return;

    float2* p = reinterpret_cast<float2*>(out + (size_t)warp * D) + lane;
    float2 v = *p;
    float ss = v.x * v.x + v.y * v.y;
    #pragma unroll
    for (int o = 16; o; o >>= 1)
        ss += __shfl_xor_sync(0xFFFFFFFFu, ss, o);
    float scale = 1.0f / fmaxf(sqrtf(ss), 1e-12f);
    v.x *= scale;
    v.y *= scale;
    *p = v;
}

// ---------------------------------------------------------------------------
// Launch
// ---------------------------------------------------------------------------
extern "C" void kernel_launch(void* const* d_in, const int* in_sizes, int n_in,
                              void* d_out, int out_size)
{
    const float* feat_a = (const float*)d_in[0];
    const float* W_a    = (const float*)d_in[1];
    const float* b_a    = (const float*)d_in[2];
    const float* feat_b = (const float*)d_in[3];
    const float* W_b    = (const float*)d_in[4];
    const float* b_b    = (const float*)d_in[5];
    const float* feat_c = (const float*)d_in[6];
    const float* W_c    = (const float*)d_in[7];
    const float* b_c    = (const float*)d_in[8];
    const float* gcnW   = (const float*)d_in[9];
    const float* gcnb   = (const float*)d_in[10];
    const float* ew     = (const float*)d_in[11];
    const int*   es     = (const int*)d_in[12];
    const int*   ed     = (const int*)d_in[13];
    float* out = (float*)d_out;

    const int na = in_sizes[0] / 512;
    const int nb = in_sizes[3] / 256;
    const int nc = in_sizes[6] / 128;
    const int N  = na + nb + nc;
    const int E  = in_sizes[11];

    // Zero the accumulator (independent of encoders; stream-ordered first).
    {
        int n4 = N * (D / 4);
        zero_kernel<<<(n4 + 255) / 256, 256>>>((float4*)out, n4);
    }

    encode_kernel<512><<<(na + 63) / 64, 256>>>(feat_a, W_a, b_a, gcnW, gcnb, na, 0);
    encode_kernel<256><<<(nb + 63) / 64, 256>>>(feat_b, W_b, b_b, gcnW, gcnb, nb, na);
    encode_kernel<128><<<(nc + 63) / 64, 256>>>(feat_c, W_c, b_c, gcnW, gcnb, nc, na + nb);

    {
        long long work = (long long)E * 16;
        int blocks = (int)((work + 255) / 256);
        scatter_kernel<<<blocks, 256>>>(ew, es, ed, out, E);
    }

    normalize_kernel<<<(N + 7) / 8, 256>>>(out, N);
}

// round 5
// speedup vs baseline: 1.4114x; 1.4114x over previous
#include <cuda_runtime.h>
#include <cuda_bf16.h>
#include <cstdint>

// ---------------------------------------------------------------------------
// NSHE: 3x per-type linear+ReLU encoders (bf16x3 split-precision tensor-core
// GEMM) fused with gcn GEMM (+bias) -> edge scatter-add -> row L2 normalize.
// ---------------------------------------------------------------------------

#define MAX_N 200000
#define D 64

__device__ float g_support[(size_t)MAX_N * D];

// ---------------- tensor-core helpers ----------------

__device__ __forceinline__ void mma_bf16(float* c, uint32_t a0, uint32_t a1,
                                         uint32_t a2, uint32_t a3,
                                         uint32_t b0, uint32_t b1)
{
    asm volatile(
        "mma.sync.aligned.m16n8k16.row.col.f32.bf16.bf16.f32 "
        "{%0,%1,%2,%3}, {%4,%5,%6,%7}, {%8,%9}, {%0,%1,%2,%3};"
        : "+f"(c[0]), "+f"(c[1]), "+f"(c[2]), "+f"(c[3])
        : "r"(a0), "r"(a1), "r"(a2), "r"(a3), "r"(b0), "r"(b1));
}

__device__ __forceinline__ void ldsm_x4(uint32_t* r, uint32_t addr)
{
    asm volatile("ldmatrix.sync.aligned.m8n8.x4.shared.b16 {%0,%1,%2,%3}, [%4];"
                 : "=r"(r[0]), "=r"(r[1]), "=r"(r[2]), "=r"(r[3]) : "r"(addr));
}

__device__ __forceinline__ void ldsm_x4_t(uint32_t* r, uint32_t addr)
{
    asm volatile("ldmatrix.sync.aligned.m8n8.x4.trans.shared.b16 {%0,%1,%2,%3}, [%4];"
                 : "=r"(r[0]), "=r"(r[1]), "=r"(r[2]), "=r"(r[3]) : "r"(addr));
}

// Split (x,y) into bf16 hi pair + bf16 residual pair. Lower 16 bits = x.
__device__ __forceinline__ void split2(float x, float y, uint32_t& hp, uint32_t& lp)
{
    __nv_bfloat162 h = __floats2bfloat162_rn(x, y);
    hp = *reinterpret_cast<uint32_t*>(&h);
    float rx = x - __bfloat162float(h.x);
    float ry = y - __bfloat162float(h.y);
    __nv_bfloat162 l = __floats2bfloat162_rn(rx, ry);
    lp = *reinterpret_cast<uint32_t*>(&l);
}

__device__ __forceinline__ uint32_t sptr(const void* p)
{
    return (uint32_t)__cvta_generic_to_shared(p);
}

// ---------------------------------------------------------------------------
// Encoder + fused gcn GEMM (tensor cores).
// Block: 128 threads (4 warps). Tile: 64 rows x 64 cols. Warp: 16 rows.
// Phase 1: enc = relu(feat[64xK] @ W[Kx64] + b)  (bf16x3, K chunked by 32)
// Phase 2: support = enc @ gcnW + gcnb           (A frags built from acc regs)
// ---------------------------------------------------------------------------
template <int K>
__global__ __launch_bounds__(128) void encode_kernel(
    const float* __restrict__ feat, const float* __restrict__ W,
    const float* __restrict__ bias, const float* __restrict__ gcnW,
    const float* __restrict__ gcnb, int n_rows, int row_offset)
{
    // Row pads (40, 72) keep ldmatrix row addresses distinct mod 8 bank-groups
    // and 16B-aligned.
    __shared__ __nv_bfloat16 SAh[64][40], SAl[64][40];   // feat tile hi/lo
    __shared__ __nv_bfloat16 SBh[32][72], SBl[32][72];   // W chunk hi/lo
    __shared__ __nv_bfloat16 GWh[64][72], GWl[64][72];   // gcnW hi/lo

    const int tid  = threadIdx.x;
    const int lane = tid & 31;
    const int wid  = tid >> 5;
    const int wr   = wid * 16;                 // warp row base within tile
    const int m0   = blockIdx.x * 64;

    // --- load gcnW into smem (hi/lo split), disjoint from phase-1 buffers ---
    #pragma unroll
    for (int j = 0; j < 8; j++) {
        int q = tid + j * 128;                  // 0..1023 float4s
        int r = q >> 4, f = q & 15;
        float4 v = *reinterpret_cast<const float4*>(&gcnW[r * 64 + f * 4]);
        uint32_t hp, lp;
        split2(v.x, v.y, hp, lp);
        *reinterpret_cast<uint32_t*>(&GWh[r][f * 4])     = hp;
        *reinterpret_cast<uint32_t*>(&GWl[r][f * 4])     = lp;
        split2(v.z, v.w, hp, lp);
        *reinterpret_cast<uint32_t*>(&GWh[r][f * 4 + 2]) = hp;
        *reinterpret_cast<uint32_t*>(&GWl[r][f * 4 + 2]) = lp;
    }

    float acc[8][4];
    #pragma unroll
    for (int j = 0; j < 8; j++)
        #pragma unroll
        for (int i = 0; i < 4; i++) acc[j][i] = 0.0f;

    // ldmatrix lane-address components
    const int a_m   = wr + (lane & 7) + (lane & 8);       // A row
    const int a_koff = (lane & 16) ? 8 : 0;               // A col offset
    const int b_k   = (lane & 7) + (lane & 8);            // B k row
    const int b_noff = (lane & 16) ? 8 : 0;               // B n offset

    for (int kk = 0; kk < K; kk += 32) {
        // ---- fill SA (64 rows x 32 k) ----
        #pragma unroll
        for (int j = 0; j < 4; j++) {
            int q = tid + j * 128;              // 0..511 float4s
            int r = q >> 3, f = q & 7;
            int grow = m0 + r;
            float4 v = make_float4(0.f, 0.f, 0.f, 0.f);
            if (grow < n_rows)
                v = *reinterpret_cast<const float4*>(&feat[(size_t)grow * K + kk + f * 4]);
            uint32_t hp, lp;
            split2(v.x, v.y, hp, lp);
            *reinterpret_cast<uint32_t*>(&SAh[r][f * 4])     = hp;
            *reinterpret_cast<uint32_t*>(&SAl[r][f * 4])     = lp;
            split2(v.z, v.w, hp, lp);
            *reinterpret_cast<uint32_t*>(&SAh[r][f * 4 + 2]) = hp;
            *reinterpret_cast<uint32_t*>(&SAl[r][f * 4 + 2]) = lp;
        }
        // ---- fill SB (32 k x 64 n) ----
        #pragma unroll
        for (int j = 0; j < 4; j++) {
            int q = tid + j * 128;
            int r = q >> 4, f = q & 15;
            float4 v = *reinterpret_cast<const float4*>(&W[(size_t)(kk + r) * 64 + f * 4]);
            uint32_t hp, lp;
            split2(v.x, v.y, hp, lp);
            *reinterpret_cast<uint32_t*>(&SBh[r][f * 4])     = hp;
            *reinterpret_cast<uint32_t*>(&SBl[r][f * 4])     = lp;
            split2(v.z, v.w, hp, lp);
            *reinterpret_cast<uint32_t*>(&SBh[r][f * 4 + 2]) = hp;
            *reinterpret_cast<uint32_t*>(&SBl[r][f * 4 + 2]) = lp;
        }
        __syncthreads();

        #pragma unroll
        for (int kc2 = 0; kc2 < 2; kc2++) {
            const int kc = kc2 * 16;
            uint32_t ah[4], al[4];
            ldsm_x4(ah, sptr(&SAh[a_m][kc + a_koff]));
            ldsm_x4(al, sptr(&SAl[a_m][kc + a_koff]));
            #pragma unroll
            for (int t = 0; t < 4; t++) {        // n-tile pairs (2t, 2t+1)
                uint32_t bh[4], bl[4];
                ldsm_x4_t(bh, sptr(&SBh[kc + b_k][16 * t + b_noff]));
                ldsm_x4_t(bl, sptr(&SBl[kc + b_k][16 * t + b_noff]));
                mma_bf16(acc[2 * t],     ah[0], ah[1], ah[2], ah[3], bh[0], bh[1]);
                mma_bf16(acc[2 * t],     ah[0], ah[1], ah[2], ah[3], bl[0], bl[1]);
                mma_bf16(acc[2 * t],     al[0], al[1], al[2], al[3], bh[0], bh[1]);
                mma_bf16(acc[2 * t + 1], ah[0], ah[1], ah[2], ah[3], bh[2], bh[3]);
                mma_bf16(acc[2 * t + 1], ah[0], ah[1], ah[2], ah[3], bl[2], bl[3]);
                mma_bf16(acc[2 * t + 1], al[0], al[1], al[2], al[3], bh[2], bh[3]);
            }
        }
        __syncthreads();
    }

    // ---- epilogue 1: bias + ReLU (in registers) ----
    const int tg = lane & 3;            // thread-in-group -> column pair
    const int g  = lane >> 2;           // group -> row
    #pragma unroll
    for (int j = 0; j < 8; j++) {
        float2 bv = *reinterpret_cast<const float2*>(&bias[8 * j + 2 * tg]);
        acc[j][0] = fmaxf(acc[j][0] + bv.x, 0.0f);
        acc[j][1] = fmaxf(acc[j][1] + bv.y, 0.0f);
        acc[j][2] = fmaxf(acc[j][2] + bv.x, 0.0f);
        acc[j][3] = fmaxf(acc[j][3] + bv.y, 0.0f);
    }

    // ---- phase 2: A fragments built directly from accumulators ----
    // C-frag (row g / g+8, cols 8j+2tg,+1) == A-frag layout for k-chunk 16q
    // covering tiles 2q (a0,a1) and 2q+1 (a2,a3).
    uint32_t a2h[4][4], a2l[4][4];
    #pragma unroll
    for (int q = 0; q < 4; q++) {
        split2(acc[2 * q][0],     acc[2 * q][1],     a2h[q][0], a2l[q][0]);
        split2(acc[2 * q][2],     acc[2 * q][3],     a2h[q][1], a2l[q][1]);
        split2(acc[2 * q + 1][0], acc[2 * q + 1][1], a2h[q][2], a2l[q][2]);
        split2(acc[2 * q + 1][2], acc[2 * q + 1][3], a2h[q][3], a2l[q][3]);
    }

    float acc2[8][4];
    #pragma unroll
    for (int j = 0; j < 8; j++)
        #pragma unroll
        for (int i = 0; i < 4; i++) acc2[j][i] = 0.0f;

    #pragma unroll
    for (int q = 0; q < 4; q++) {
        const int kc = 16 * q;
        #pragma unroll
        for (int t = 0; t < 4; t++) {
            uint32_t bh[4], bl[4];
            ldsm_x4_t(bh, sptr(&GWh[kc + b_k][16 * t + b_noff]));
            ldsm_x4_t(bl, sptr(&GWl[kc + b_k][16 * t + b_noff]));
            mma_bf16(acc2[2 * t],     a2h[q][0], a2h[q][1], a2h[q][2], a2h[q][3], bh[0], bh[1]);
            mma_bf16(acc2[2 * t],     a2h[q][0], a2h[q][1], a2h[q][2], a2h[q][3], bl[0], bl[1]);
            mma_bf16(acc2[2 * t],     a2l[q][0], a2l[q][1], a2l[q][2], a2l[q][3], bh[0], bh[1]);
            mma_bf16(acc2[2 * t + 1], a2h[q][0], a2h[q][1], a2h[q][2], a2h[q][3], bh[2], bh[3]);
            mma_bf16(acc2[2 * t + 1], a2h[q][0], a2h[q][1], a2h[q][2], a2h[q][3], bl[2], bl[3]);
            mma_bf16(acc2[2 * t + 1], a2l[q][0], a2l[q][1], a2l[q][2], a2l[q][3], bh[2], bh[3]);
        }
    }

    // ---- epilogue 2: + gcnb, store to g_support ----
    const int r_lo = m0 + wr + g;
    const int r_hi = r_lo + 8;
    #pragma unroll
    for (int j = 0; j < 8; j++) {
        int c = 8 * j + 2 * tg;
        float2 gb = *reinterpret_cast<const float2*>(&gcnb[c]);
        if (r_lo < n_rows) {
            float2 o = make_float2(acc2[j][0] + gb.x, acc2[j][1] + gb.y);
            *reinterpret_cast<float2*>(&g_support[(size_t)(row_offset + r_lo) * D + c]) = o;
        }
        if (r_hi < n_rows) {
            float2 o = make_float2(acc2[j][2] + gb.x, acc2[j][3] + gb.y);
            *reinterpret_cast<float2*>(&g_support[(size_t)(row_offset + r_hi) * D + c]) = o;
        }
    }
}

// ---------------------------------------------------------------------------
__global__ void zero_kernel(float4* __restrict__ out, int n4)
{
    int i = blockIdx.x * blockDim.x + threadIdx.x;
    if (i < n4) out[i] = make_float4(0.0f, 0.0f, 0.0f, 0.0f);
}

__global__ void scatter_kernel(const float* __restrict__ ew,
                               const int* __restrict__ es,
                               const int* __restrict__ ed,
                               float* __restrict__ out, int E)
{
    unsigned gid = blockIdx.x * blockDim.x + threadIdx.x;
    unsigned e = gid >> 4;
    if (e >= (unsigned)E) return;
    int c4 = (gid & 15) << 2;

    int s = __ldg(&es[e]);
    int d = __ldg(&ed[e]);
    float w = __ldg(&ew[e]);

    float4 v = *reinterpret_cast<const float4*>(&g_support[(size_t)s * D + c4]);
    float* p = out + (size_t)d * D + c4;
    asm volatile("red.global.add.v4.f32 [%0], {%1, %2, %3, %4};"
                 :: "l"(p), "f"(v.x * w), "f"(v.y * w), "f"(v.z * w), "f"(v.w * w)
                 : "memory");
}

__global__ void normalize_kernel(float* __restrict__ out, int N)
{
    int warp = (blockIdx.x * blockDim.x + threadIdx.x) >> 5;
    int lane = threadIdx.x & 31;
    if (warp >= N) return;

    float2* p = reinterpret_cast<float2*>(out + (size_t)warp * D) + lane;
    float2 v = *p;
    float ss = v.x * v.x + v.y * v.y;
    #pragma unroll
    for (int o = 16; o; o >>= 1)
        ss += __shfl_xor_sync(0xFFFFFFFFu, ss, o);
    float scale = 1.0f / fmaxf(sqrtf(ss), 1e-12f);
    v.x *= scale;
    v.y *= scale;
    *p = v;
}

// ---------------------------------------------------------------------------
extern "C" void kernel_launch(void* const* d_in, const int* in_sizes, int n_in,
                              void* d_out, int out_size)
{
    const float* feat_a = (const float*)d_in[0];
    const float* W_a    = (const float*)d_in[1];
    const float* b_a    = (const float*)d_in[2];
    const float* feat_b = (const float*)d_in[3];
    const float* W_b    = (const float*)d_in[4];
    const float* b_b    = (const float*)d_in[5];
    const float* feat_c = (const float*)d_in[6];
    const float* W_c    = (const float*)d_in[7];
    const float* b_c    = (const float*)d_in[8];
    const float* gcnW   = (const float*)d_in[9];
    const float* gcnb   = (const float*)d_in[10];
    const float* ew     = (const float*)d_in[11];
    const int*   es     = (const int*)d_in[12];
    const int*   ed     = (const int*)d_in[13];
    float* out = (float*)d_out;

    const int na = in_sizes[0] / 512;
    const int nb = in_sizes[3] / 256;
    const int nc = in_sizes[6] / 128;
    const int N  = na + nb + nc;
    const int E  = in_sizes[11];

    {
        int n4 = N * (D / 4);
        zero_kernel<<<(n4 + 255) / 256, 256>>>((float4*)out, n4);
    }

    encode_kernel<512><<<(na + 63) / 64, 128>>>(feat_a, W_a, b_a, gcnW, gcnb, na, 0);
    encode_kernel<256><<<(nb + 63) / 64, 128>>>(feat_b, W_b, b_b, gcnW, gcnb, nb, na);
    encode_kernel<128><<<(nc + 63) / 64, 128>>>(feat_c, W_c, b_c, gcnW, gcnb, nc, na + nb);

    {
        long long work = (long long)E * 16;
        int blocks = (int)((work + 255) / 256);
        scatter_kernel<<<blocks, 256>>>(ew, es, ed, out, E);
    }

    normalize_kernel<<<(N + 7) / 8, 256>>>(out, N);
}